// round 9
// baseline (speedup 1.0000x reference)
#include <cuda_runtime.h>
#include <cuda_bf16.h>
#include <cstdint>

#define N_NODES  50000
#define N_EDGES  800000
#define IN_F     512
#define OUT_F    96
#define ALPHA    0.1f
#define ITERS    10
#define SCAN_BLK 512
#define NBLK     ((N_NODES + SCAN_BLK - 1) / SCAN_BLK)   // 98

// ---- device-global scratch (allocation-free per harness rules) -------------
__device__ float g_support[(size_t)N_NODES * OUT_F];
__device__ float g_bufA[(size_t)N_NODES * OUT_F];
__device__ float g_bufB[(size_t)N_NODES * OUT_F];
__device__ int   g_rowptr[N_NODES + 1];
__device__ int   g_cursor[N_NODES];
__device__ int   g_deg[N_NODES];
__device__ int   g_blocksum[NBLK];
__device__ int   g_blockoff[NBLK];
__device__ int   g_esrc[N_EDGES];
__device__ float g_eval[N_EDGES];
// W split into bf16 hi/lo, transposed to [OUT_F][IN_F]
__device__ __align__(16) __nv_bfloat16 g_WhiT[(size_t)OUT_F * IN_F];
__device__ __align__(16) __nv_bfloat16 g_WloT[(size_t)OUT_F * IN_F];

// ---------------------------------------------------------------------------
// helpers for tensor-core GEMM
// ---------------------------------------------------------------------------
__device__ __forceinline__ uint32_t smem_u32(const void* p) {
    uint32_t a;
    asm("{ .reg .u64 t; cvta.to.shared.u64 t, %1; cvt.u32.u64 %0, t; }"
        : "=r"(a) : "l"(p));
    return a;
}

__device__ __forceinline__ void ldsm_x4(uint32_t* r, uint32_t addr) {
    asm volatile("ldmatrix.sync.aligned.m8n8.x4.shared.b16 {%0,%1,%2,%3}, [%4];"
                 : "=r"(r[0]), "=r"(r[1]), "=r"(r[2]), "=r"(r[3]) : "r"(addr));
}

__device__ __forceinline__ void mma_bf16(float* d, const uint32_t* a,
                                         uint32_t b0, uint32_t b1) {
    asm volatile("mma.sync.aligned.m16n8k16.row.col.f32.bf16.bf16.f32 "
                 "{%0,%1,%2,%3}, {%4,%5,%6,%7}, {%8,%9}, {%0,%1,%2,%3};"
                 : "+f"(d[0]), "+f"(d[1]), "+f"(d[2]), "+f"(d[3])
                 : "r"(a[0]), "r"(a[1]), "r"(a[2]), "r"(a[3]),
                   "r"(b0), "r"(b1));
}

// ---------------------------------------------------------------------------
// W preconvert: split fp32 W[512,96] into bf16 hi/lo, transposed [96][512]
// ---------------------------------------------------------------------------
__global__ void wconv_kernel(const float* __restrict__ W) {
    int i = blockIdx.x * blockDim.x + threadIdx.x;
    if (i < IN_F * OUT_F) {
        int k = i / OUT_F, n = i % OUT_F;
        float w = W[i];
        __nv_bfloat16 hi = __float2bfloat16_rn(w);
        float lo = w - __bfloat162float(hi);
        g_WhiT[(size_t)n * IN_F + k] = hi;
        g_WloT[(size_t)n * IN_F + k] = __float2bfloat16_rn(lo);
    }
}

// ---------------------------------------------------------------------------
// GEMM via mma.sync bf16 split: support = X @ W
// ---------------------------------------------------------------------------
#define SMS 144   // bytes per smem row
#define A_HI_OFF 0
#define A_LO_OFF 18432         // 128*144
#define B_HI_OFF 36864
#define B_LO_OFF 50688
#define GEMM_SMEM 64512

__global__ __launch_bounds__(256, 2) void gemm_mma_kernel(
    const float* __restrict__ X, float* __restrict__ out)
{
    extern __shared__ char sm[];
    char* As_hi = sm + A_HI_OFF;
    char* As_lo = sm + A_LO_OFF;
    char* Bs_hi = sm + B_HI_OFF;
    char* Bs_lo = sm + B_LO_OFF;

    const int tid  = threadIdx.x;
    const int lane = tid & 31;
    const int wid  = tid >> 5;
    const int wm   = wid >> 1;
    const int wn   = wid & 1;
    const int ctaM = blockIdx.x * 128;

    float acc[2][6][4];
#pragma unroll
    for (int mt = 0; mt < 2; ++mt)
#pragma unroll
        for (int nt = 0; nt < 6; ++nt)
#pragma unroll
            for (int r = 0; r < 4; ++r) acc[mt][nt][r] = 0.0f;

    const uint32_t a_hi = smem_u32(As_hi);
    const uint32_t a_lo = smem_u32(As_lo);
    const uint32_t b_hi = smem_u32(Bs_hi);
    const uint32_t b_lo = smem_u32(Bs_lo);

    const int a_row = ((lane >> 3) & 1) * 8 + (lane & 7);
    const int a_kh  = lane >> 4;
    const int b_row = ((lane >> 4) & 1) * 8 + (lane & 7);
    const int b_kh  = (lane >> 3) & 1;

    for (int k0 = 0; k0 < IN_F; k0 += 64) {
#pragma unroll
        for (int j = 0; j < 8; ++j) {
            int i   = tid + j * 256;
            int row = i >> 4;
            int kg  = i & 15;
            int grow = ctaM + row;
            if (grow >= N_NODES) grow = N_NODES - 1;
            float4 v = *reinterpret_cast<const float4*>(
                X + (size_t)grow * IN_F + k0 + kg * 4);
            __nv_bfloat16 h0 = __float2bfloat16_rn(v.x);
            __nv_bfloat16 h1 = __float2bfloat16_rn(v.y);
            __nv_bfloat16 h2 = __float2bfloat16_rn(v.z);
            __nv_bfloat16 h3 = __float2bfloat16_rn(v.w);
            char* ph = As_hi + row * SMS + kg * 8;
            *reinterpret_cast<__nv_bfloat162*>(ph)     = __halves2bfloat162(h0, h1);
            *reinterpret_cast<__nv_bfloat162*>(ph + 4) = __halves2bfloat162(h2, h3);
            __nv_bfloat16 l0 = __float2bfloat16_rn(v.x - __bfloat162float(h0));
            __nv_bfloat16 l1 = __float2bfloat16_rn(v.y - __bfloat162float(h1));
            __nv_bfloat16 l2 = __float2bfloat16_rn(v.z - __bfloat162float(h2));
            __nv_bfloat16 l3 = __float2bfloat16_rn(v.w - __bfloat162float(h3));
            char* pl = As_lo + row * SMS + kg * 8;
            *reinterpret_cast<__nv_bfloat162*>(pl)     = __halves2bfloat162(l0, l1);
            *reinterpret_cast<__nv_bfloat162*>(pl + 4) = __halves2bfloat162(l2, l3);
        }
#pragma unroll
        for (int j = 0; j < 3; ++j) {
            int i   = tid + j * 256;
            int row = i >> 3;
            int kg  = i & 7;
            size_t goff = ((size_t)row * IN_F + k0) * 2 + kg * 16;
            *reinterpret_cast<uint4*>(Bs_hi + row * SMS + kg * 16) =
                *reinterpret_cast<const uint4*>(
                    reinterpret_cast<const char*>(g_WhiT) + goff);
            *reinterpret_cast<uint4*>(Bs_lo + row * SMS + kg * 16) =
                *reinterpret_cast<const uint4*>(
                    reinterpret_cast<const char*>(g_WloT) + goff);
        }
        __syncthreads();

#pragma unroll
        for (int ks = 0; ks < 4; ++ks) {
            uint32_t Ah[2][4], Al[2][4];
#pragma unroll
            for (int mt = 0; mt < 2; ++mt) {
                uint32_t off = (uint32_t)((wm * 32 + mt * 16 + a_row) * SMS
                                          + ks * 32 + a_kh * 16);
                ldsm_x4(Ah[mt], a_hi + off);
                ldsm_x4(Al[mt], a_lo + off);
            }
            uint32_t Bh[3][4], Bl[3][4];
#pragma unroll
            for (int np = 0; np < 3; ++np) {
                uint32_t off = (uint32_t)((wn * 48 + np * 16 + b_row) * SMS
                                          + ks * 32 + b_kh * 16);
                ldsm_x4(Bh[np], b_hi + off);
                ldsm_x4(Bl[np], b_lo + off);
            }
#pragma unroll
            for (int mt = 0; mt < 2; ++mt)
#pragma unroll
                for (int nt = 0; nt < 6; ++nt) {
                    uint32_t bh0 = Bh[nt >> 1][(nt & 1) * 2];
                    uint32_t bh1 = Bh[nt >> 1][(nt & 1) * 2 + 1];
                    uint32_t bl0 = Bl[nt >> 1][(nt & 1) * 2];
                    uint32_t bl1 = Bl[nt >> 1][(nt & 1) * 2 + 1];
                    mma_bf16(acc[mt][nt], Ah[mt], bh0, bh1);
                    mma_bf16(acc[mt][nt], Ah[mt], bl0, bl1);
                    mma_bf16(acc[mt][nt], Al[mt], bh0, bh1);
                }
        }
        __syncthreads();
    }

#pragma unroll
    for (int mt = 0; mt < 2; ++mt) {
        int row0 = ctaM + wm * 32 + mt * 16 + (lane >> 2);
#pragma unroll
        for (int nt = 0; nt < 6; ++nt) {
            int col = wn * 48 + nt * 8 + (lane & 3) * 2;
            if (row0 < N_NODES) {
                float2 v = make_float2(acc[mt][nt][0], acc[mt][nt][1]);
                *reinterpret_cast<float2*>(out + (size_t)row0 * OUT_F + col) = v;
            }
            int row1 = row0 + 8;
            if (row1 < N_NODES) {
                float2 v = make_float2(acc[mt][nt][2], acc[mt][nt][3]);
                *reinterpret_cast<float2*>(out + (size_t)row1 * OUT_F + col) = v;
            }
        }
    }
}

// ---------------------------------------------------------------------------
// CSR build: histogram -> scan -> fill
// ---------------------------------------------------------------------------
__global__ void zero_deg_kernel() {
    int i = blockIdx.x * blockDim.x + threadIdx.x;
    if (i < N_NODES) g_deg[i] = 0;
}

__global__ void hist_kernel(const int* __restrict__ dst) {
    int i = blockIdx.x * blockDim.x + threadIdx.x;
    if (i < N_EDGES) atomicAdd(&g_deg[dst[i]], 1);
}

__global__ __launch_bounds__(SCAN_BLK) void scan1_kernel() {
    __shared__ int sh[SCAN_BLK];
    int t = threadIdx.x;
    int gi = blockIdx.x * SCAN_BLK + t;
    int v = (gi < N_NODES) ? g_deg[gi] : 0;
    sh[t] = v;
    __syncthreads();
#pragma unroll
    for (int off = 1; off < SCAN_BLK; off <<= 1) {
        int x = (t >= off) ? sh[t - off] : 0;
        __syncthreads();
        sh[t] += x;
        __syncthreads();
    }
    if (gi < N_NODES) g_rowptr[gi] = sh[t] - v;
    if (t == SCAN_BLK - 1) g_blocksum[blockIdx.x] = sh[t];
}

__global__ __launch_bounds__(128) void scan2_kernel() {
    __shared__ int sh[128];
    int t = threadIdx.x;
    int v = (t < NBLK) ? g_blocksum[t] : 0;
    sh[t] = v;
    __syncthreads();
#pragma unroll
    for (int off = 1; off < 128; off <<= 1) {
        int x = (t >= off) ? sh[t - off] : 0;
        __syncthreads();
        sh[t] += x;
        __syncthreads();
    }
    if (t < NBLK) g_blockoff[t] = sh[t] - v;
}

__global__ void scan3_kernel() {
    int i = blockIdx.x * blockDim.x + threadIdx.x;
    if (i < N_NODES) {
        int r = g_rowptr[i] + g_blockoff[i / SCAN_BLK];
        g_rowptr[i] = r;
        g_cursor[i] = r;
    }
    if (i == 0) g_rowptr[N_NODES] = N_EDGES;
}

__global__ void fill_kernel(const int* __restrict__ src,
                            const int* __restrict__ dst,
                            const float* __restrict__ val) {
    int i = blockIdx.x * blockDim.x + threadIdx.x;
    if (i < N_EDGES) {
        int pos = atomicAdd(&g_cursor[dst[i]], 1);
        g_esrc[pos] = src[i];
        g_eval[pos] = val[i] * (1.0f - ALPHA);
    }
}

// ---------------------------------------------------------------------------
// SpMM: warp = (node, feature-third). 3 warps per node, 1 gather per edge.
// Low register pressure -> high occupancy -> more latency hiding.
//   out[d, fg*32+lane] = ALPHA*sup[d, ...] + sum_e val[e]*reluIn?(cur[src[e], ...])
// ---------------------------------------------------------------------------
template <int RELU_IN, int RELU_OUT>
__global__ __launch_bounds__(256) void spmm_kernel(
    const float* __restrict__ cur, const float* __restrict__ sup,
    float* __restrict__ out)
{
    const int gwarp = (blockIdx.x * 256 + threadIdx.x) >> 5;
    const int lane  = threadIdx.x & 31;
    if (gwarp >= N_NODES * 3) return;
    const int node = gwarp / 3;
    const int foff = (gwarp - node * 3) * 32 + lane;   // feature index

    const int beg = __ldg(&g_rowptr[node]);
    const int end = __ldg(&g_rowptr[node + 1]);

    float acc = 0.f;

    int i = beg;
    for (; i + 4 <= end; i += 4) {
        int   s0 = __ldg(&g_esrc[i]),     s1 = __ldg(&g_esrc[i + 1]);
        int   s2 = __ldg(&g_esrc[i + 2]), s3 = __ldg(&g_esrc[i + 3]);
        float v0 = __ldg(&g_eval[i]),     v1 = __ldg(&g_eval[i + 1]);
        float v2 = __ldg(&g_eval[i + 2]), v3 = __ldg(&g_eval[i + 3]);
        float x0 = __ldg(cur + (size_t)s0 * OUT_F + foff);
        float x1 = __ldg(cur + (size_t)s1 * OUT_F + foff);
        float x2 = __ldg(cur + (size_t)s2 * OUT_F + foff);
        float x3 = __ldg(cur + (size_t)s3 * OUT_F + foff);
        if (RELU_IN) {
            x0 = fmaxf(x0, 0.f); x1 = fmaxf(x1, 0.f);
            x2 = fmaxf(x2, 0.f); x3 = fmaxf(x3, 0.f);
        }
        acc = fmaf(v0, x0, acc);
        acc = fmaf(v1, x1, acc);
        acc = fmaf(v2, x2, acc);
        acc = fmaf(v3, x3, acc);
    }
    for (; i < end; ++i) {
        int   s0 = __ldg(&g_esrc[i]);
        float v0 = __ldg(&g_eval[i]);
        float x0 = __ldg(cur + (size_t)s0 * OUT_F + foff);
        if (RELU_IN) x0 = fmaxf(x0, 0.f);
        acc = fmaf(v0, x0, acc);
    }

    float r = fmaf(ALPHA, __ldg(sup + (size_t)node * OUT_F + foff), acc);
    if (RELU_OUT) r = fmaxf(r, 0.f);
    out[(size_t)node * OUT_F + foff] = r;
}

// ---------------------------------------------------------------------------
extern "C" void kernel_launch(void* const* d_in, const int* in_sizes, int n_in,
                              void* d_out, int out_size)
{
    const float* x    = (const float*)d_in[0];
    const float* w    = (const float*)d_in[1];
    const int*   src  = (const int*)d_in[2];
    const int*   dst  = (const int*)d_in[3];
    const float* val  = (const float*)d_in[4];
    float*       out  = (float*)d_out;

    float *sup, *bufA, *bufB;
    cudaGetSymbolAddress((void**)&sup,  g_support);
    cudaGetSymbolAddress((void**)&bufA, g_bufA);
    cudaGetSymbolAddress((void**)&bufB, g_bufB);

    // Side stream + events for capture fork-join (host-side resources only).
    static cudaStream_t s_csr = nullptr;
    static cudaEvent_t  ev_fork = nullptr, ev_join = nullptr;
    if (!s_csr) {
        cudaStreamCreateWithFlags(&s_csr, cudaStreamNonBlocking);
        cudaEventCreateWithFlags(&ev_fork, cudaEventDisableTiming);
        cudaEventCreateWithFlags(&ev_join, cudaEventDisableTiming);
    }

    cudaFuncSetAttribute(gemm_mma_kernel,
                         cudaFuncAttributeMaxDynamicSharedMemorySize, GEMM_SMEM);

    // ---- fork: CSR build on side stream, GEMM on main stream ----
    cudaEventRecord(ev_fork, 0);
    cudaStreamWaitEvent(s_csr, ev_fork, 0);

    // branch A (main stream): W preconvert + GEMM
    wconv_kernel<<<(IN_F * OUT_F + 255) / 256, 256>>>(w);
    gemm_mma_kernel<<<(N_NODES + 127) / 128, 256, GEMM_SMEM>>>(x, sup);

    // branch B (side stream): CSR build (dst-sorted adjacency)
    zero_deg_kernel<<<(N_NODES + 255) / 256, 256, 0, s_csr>>>();
    hist_kernel<<<(N_EDGES + 255) / 256, 256, 0, s_csr>>>(dst);
    scan1_kernel<<<NBLK, SCAN_BLK, 0, s_csr>>>();
    scan2_kernel<<<1, 128, 0, s_csr>>>();
    scan3_kernel<<<(N_NODES + 255) / 256, 256, 0, s_csr>>>();
    fill_kernel<<<(N_EDGES + 255) / 256, 256, 0, s_csr>>>(src, dst, val);

    // ---- join ----
    cudaEventRecord(ev_join, s_csr);
    cudaStreamWaitEvent(0, ev_join, 0);

    // 10 propagation iterations, 3 warps per node (one per feature third)
    const int spmmBlocks = (N_NODES * 3 * 32 + 255) / 256;   // 18750
    const float* cur = sup;
    for (int it = 0; it < ITERS; ++it) {
        float* nxt = (it == ITERS - 1) ? out : ((it & 1) ? bufB : bufA);
        if (it == 0)
            spmm_kernel<0, 0><<<spmmBlocks, 256>>>(cur, sup, nxt);
        else if (it == ITERS - 1)
            spmm_kernel<1, 1><<<spmmBlocks, 256>>>(cur, sup, nxt);
        else
            spmm_kernel<1, 0><<<spmmBlocks, 256>>>(cur, sup, nxt);
        cur = nxt;
    }
}

// round 11
// speedup vs baseline: 1.7073x; 1.7073x over previous
#include <cuda_runtime.h>
#include <cuda_bf16.h>
#include <cstdint>

#define N_NODES  50000
#define N_EDGES  800000
#define IN_F     512
#define OUT_F    96
#define ALPHA    0.1f
#define ITERS    10
#define SCAN_BLK 512
#define NBLK     ((N_NODES + SCAN_BLK - 1) / SCAN_BLK)   // 98

// ---- device-global scratch (allocation-free per harness rules) -------------
__device__ float g_support[(size_t)N_NODES * OUT_F];
__device__ float g_bufA[(size_t)N_NODES * OUT_F];
__device__ float g_bufB[(size_t)N_NODES * OUT_F];
__device__ int   g_rowptr[N_NODES + 1];
__device__ int   g_cursor[N_NODES];
__device__ int   g_deg[N_NODES];
__device__ int   g_blocksum[NBLK];
__device__ int   g_blockoff[NBLK];
__device__ __align__(16) int2 g_epack[N_EDGES];   // {src, bits(0.9*val)}
// W split into bf16 hi/lo, transposed to [OUT_F][IN_F]
__device__ __align__(16) __nv_bfloat16 g_WhiT[(size_t)OUT_F * IN_F];
__device__ __align__(16) __nv_bfloat16 g_WloT[(size_t)OUT_F * IN_F];

// ---------------------------------------------------------------------------
// helpers for tensor-core GEMM
// ---------------------------------------------------------------------------
__device__ __forceinline__ uint32_t smem_u32(const void* p) {
    uint32_t a;
    asm("{ .reg .u64 t; cvta.to.shared.u64 t, %1; cvt.u32.u64 %0, t; }"
        : "=r"(a) : "l"(p));
    return a;
}

__device__ __forceinline__ void ldsm_x4(uint32_t* r, uint32_t addr) {
    asm volatile("ldmatrix.sync.aligned.m8n8.x4.shared.b16 {%0,%1,%2,%3}, [%4];"
                 : "=r"(r[0]), "=r"(r[1]), "=r"(r[2]), "=r"(r[3]) : "r"(addr));
}

__device__ __forceinline__ void mma_bf16(float* d, const uint32_t* a,
                                         uint32_t b0, uint32_t b1) {
    asm volatile("mma.sync.aligned.m16n8k16.row.col.f32.bf16.bf16.f32 "
                 "{%0,%1,%2,%3}, {%4,%5,%6,%7}, {%8,%9}, {%0,%1,%2,%3};"
                 : "+f"(d[0]), "+f"(d[1]), "+f"(d[2]), "+f"(d[3])
                 : "r"(a[0]), "r"(a[1]), "r"(a[2]), "r"(a[3]),
                   "r"(b0), "r"(b1));
}

// ---------------------------------------------------------------------------
// W preconvert: split fp32 W[512,96] into bf16 hi/lo, transposed [96][512]
// ---------------------------------------------------------------------------
__global__ void wconv_kernel(const float* __restrict__ W) {
    int i = blockIdx.x * blockDim.x + threadIdx.x;
    if (i < IN_F * OUT_F) {
        int k = i / OUT_F, n = i % OUT_F;
        float w = W[i];
        __nv_bfloat16 hi = __float2bfloat16_rn(w);
        float lo = w - __bfloat162float(hi);
        g_WhiT[(size_t)n * IN_F + k] = hi;
        g_WloT[(size_t)n * IN_F + k] = __float2bfloat16_rn(lo);
    }
}

// ---------------------------------------------------------------------------
// GEMM via mma.sync bf16 split: support = X @ W
// ---------------------------------------------------------------------------
#define SMS 144   // bytes per smem row
#define A_HI_OFF 0
#define A_LO_OFF 18432         // 128*144
#define B_HI_OFF 36864
#define B_LO_OFF 50688
#define GEMM_SMEM 64512

__global__ __launch_bounds__(256, 2) void gemm_mma_kernel(
    const float* __restrict__ X, float* __restrict__ out)
{
    extern __shared__ char sm[];
    char* As_hi = sm + A_HI_OFF;
    char* As_lo = sm + A_LO_OFF;
    char* Bs_hi = sm + B_HI_OFF;
    char* Bs_lo = sm + B_LO_OFF;

    const int tid  = threadIdx.x;
    const int lane = tid & 31;
    const int wid  = tid >> 5;
    const int wm   = wid >> 1;
    const int wn   = wid & 1;
    const int ctaM = blockIdx.x * 128;

    float acc[2][6][4];
#pragma unroll
    for (int mt = 0; mt < 2; ++mt)
#pragma unroll
        for (int nt = 0; nt < 6; ++nt)
#pragma unroll
            for (int r = 0; r < 4; ++r) acc[mt][nt][r] = 0.0f;

    const uint32_t a_hi = smem_u32(As_hi);
    const uint32_t a_lo = smem_u32(As_lo);
    const uint32_t b_hi = smem_u32(Bs_hi);
    const uint32_t b_lo = smem_u32(Bs_lo);

    const int a_row = ((lane >> 3) & 1) * 8 + (lane & 7);
    const int a_kh  = lane >> 4;
    const int b_row = ((lane >> 4) & 1) * 8 + (lane & 7);
    const int b_kh  = (lane >> 3) & 1;

    for (int k0 = 0; k0 < IN_F; k0 += 64) {
#pragma unroll
        for (int j = 0; j < 8; ++j) {
            int i   = tid + j * 256;
            int row = i >> 4;
            int kg  = i & 15;
            int grow = ctaM + row;
            if (grow >= N_NODES) grow = N_NODES - 1;
            float4 v = *reinterpret_cast<const float4*>(
                X + (size_t)grow * IN_F + k0 + kg * 4);
            __nv_bfloat16 h0 = __float2bfloat16_rn(v.x);
            __nv_bfloat16 h1 = __float2bfloat16_rn(v.y);
            __nv_bfloat16 h2 = __float2bfloat16_rn(v.z);
            __nv_bfloat16 h3 = __float2bfloat16_rn(v.w);
            char* ph = As_hi + row * SMS + kg * 8;
            *reinterpret_cast<__nv_bfloat162*>(ph)     = __halves2bfloat162(h0, h1);
            *reinterpret_cast<__nv_bfloat162*>(ph + 4) = __halves2bfloat162(h2, h3);
            __nv_bfloat16 l0 = __float2bfloat16_rn(v.x - __bfloat162float(h0));
            __nv_bfloat16 l1 = __float2bfloat16_rn(v.y - __bfloat162float(h1));
            __nv_bfloat16 l2 = __float2bfloat16_rn(v.z - __bfloat162float(h2));
            __nv_bfloat16 l3 = __float2bfloat16_rn(v.w - __bfloat162float(h3));
            char* pl = As_lo + row * SMS + kg * 8;
            *reinterpret_cast<__nv_bfloat162*>(pl)     = __halves2bfloat162(l0, l1);
            *reinterpret_cast<__nv_bfloat162*>(pl + 4) = __halves2bfloat162(l2, l3);
        }
#pragma unroll
        for (int j = 0; j < 3; ++j) {
            int i   = tid + j * 256;
            int row = i >> 3;
            int kg  = i & 7;
            size_t goff = ((size_t)row * IN_F + k0) * 2 + kg * 16;
            *reinterpret_cast<uint4*>(Bs_hi + row * SMS + kg * 16) =
                *reinterpret_cast<const uint4*>(
                    reinterpret_cast<const char*>(g_WhiT) + goff);
            *reinterpret_cast<uint4*>(Bs_lo + row * SMS + kg * 16) =
                *reinterpret_cast<const uint4*>(
                    reinterpret_cast<const char*>(g_WloT) + goff);
        }
        __syncthreads();

#pragma unroll
        for (int ks = 0; ks < 4; ++ks) {
            uint32_t Ah[2][4], Al[2][4];
#pragma unroll
            for (int mt = 0; mt < 2; ++mt) {
                uint32_t off = (uint32_t)((wm * 32 + mt * 16 + a_row) * SMS
                                          + ks * 32 + a_kh * 16);
                ldsm_x4(Ah[mt], a_hi + off);
                ldsm_x4(Al[mt], a_lo + off);
            }
            uint32_t Bh[3][4], Bl[3][4];
#pragma unroll
            for (int np = 0; np < 3; ++np) {
                uint32_t off = (uint32_t)((wn * 48 + np * 16 + b_row) * SMS
                                          + ks * 32 + b_kh * 16);
                ldsm_x4(Bh[np], b_hi + off);
                ldsm_x4(Bl[np], b_lo + off);
            }
#pragma unroll
            for (int mt = 0; mt < 2; ++mt)
#pragma unroll
                for (int nt = 0; nt < 6; ++nt) {
                    uint32_t bh0 = Bh[nt >> 1][(nt & 1) * 2];
                    uint32_t bh1 = Bh[nt >> 1][(nt & 1) * 2 + 1];
                    uint32_t bl0 = Bl[nt >> 1][(nt & 1) * 2];
                    uint32_t bl1 = Bl[nt >> 1][(nt & 1) * 2 + 1];
                    mma_bf16(acc[mt][nt], Ah[mt], bh0, bh1);
                    mma_bf16(acc[mt][nt], Ah[mt], bl0, bl1);
                    mma_bf16(acc[mt][nt], Al[mt], bh0, bh1);
                }
        }
        __syncthreads();
    }

#pragma unroll
    for (int mt = 0; mt < 2; ++mt) {
        int row0 = ctaM + wm * 32 + mt * 16 + (lane >> 2);
#pragma unroll
        for (int nt = 0; nt < 6; ++nt) {
            int col = wn * 48 + nt * 8 + (lane & 3) * 2;
            if (row0 < N_NODES) {
                float2 v = make_float2(acc[mt][nt][0], acc[mt][nt][1]);
                *reinterpret_cast<float2*>(out + (size_t)row0 * OUT_F + col) = v;
            }
            int row1 = row0 + 8;
            if (row1 < N_NODES) {
                float2 v = make_float2(acc[mt][nt][2], acc[mt][nt][3]);
                *reinterpret_cast<float2*>(out + (size_t)row1 * OUT_F + col) = v;
            }
        }
    }
}

// ---------------------------------------------------------------------------
// CSR build: histogram -> scan -> fill (packed src+val records)
// ---------------------------------------------------------------------------
__global__ void zero_deg_kernel() {
    int i = blockIdx.x * blockDim.x + threadIdx.x;
    if (i < N_NODES) g_deg[i] = 0;
}

__global__ void hist_kernel(const int* __restrict__ dst) {
    int i = blockIdx.x * blockDim.x + threadIdx.x;
    if (i < N_EDGES) atomicAdd(&g_deg[dst[i]], 1);
}

__global__ __launch_bounds__(SCAN_BLK) void scan1_kernel() {
    __shared__ int sh[SCAN_BLK];
    int t = threadIdx.x;
    int gi = blockIdx.x * SCAN_BLK + t;
    int v = (gi < N_NODES) ? g_deg[gi] : 0;
    sh[t] = v;
    __syncthreads();
#pragma unroll
    for (int off = 1; off < SCAN_BLK; off <<= 1) {
        int x = (t >= off) ? sh[t - off] : 0;
        __syncthreads();
        sh[t] += x;
        __syncthreads();
    }
    if (gi < N_NODES) g_rowptr[gi] = sh[t] - v;
    if (t == SCAN_BLK - 1) g_blocksum[blockIdx.x] = sh[t];
}

__global__ __launch_bounds__(128) void scan2_kernel() {
    __shared__ int sh[128];
    int t = threadIdx.x;
    int v = (t < NBLK) ? g_blocksum[t] : 0;
    sh[t] = v;
    __syncthreads();
#pragma unroll
    for (int off = 1; off < 128; off <<= 1) {
        int x = (t >= off) ? sh[t - off] : 0;
        __syncthreads();
        sh[t] += x;
        __syncthreads();
    }
    if (t < NBLK) g_blockoff[t] = sh[t] - v;
}

__global__ void scan3_kernel() {
    int i = blockIdx.x * blockDim.x + threadIdx.x;
    if (i < N_NODES) {
        int r = g_rowptr[i] + g_blockoff[i / SCAN_BLK];
        g_rowptr[i] = r;
        g_cursor[i] = r;
    }
    if (i == 0) g_rowptr[N_NODES] = N_EDGES;
}

__global__ void fill_kernel(const int* __restrict__ src,
                            const int* __restrict__ dst,
                            const float* __restrict__ val) {
    int i = blockIdx.x * blockDim.x + threadIdx.x;
    if (i < N_EDGES) {
        int pos = atomicAdd(&g_cursor[dst[i]], 1);
        g_epack[pos] = make_int2(src[i],
                                 __float_as_int(val[i] * (1.0f - ALPHA)));
    }
}

// ---------------------------------------------------------------------------
// SpMM (gather, warp-per-destination-node), fused residual + lazy ReLU.
// Identical structure to the proven 24.5us/iter config; the ONLY change is
// edge records are a single packed int2 load (4 LDGs/batch instead of 8).
// ---------------------------------------------------------------------------
template <int RELU_IN, int RELU_OUT>
__global__ __launch_bounds__(256) void spmm_kernel(
    const float* __restrict__ cur, const float* __restrict__ sup,
    float* __restrict__ out)
{
    int warp = (blockIdx.x * 256 + threadIdx.x) >> 5;
    int lane = threadIdx.x & 31;
    if (warp >= N_NODES) return;

    int beg = g_rowptr[warp];
    int end = g_rowptr[warp + 1];

    float a0 = 0.f, a1 = 0.f, a2 = 0.f;

    int i = beg;
    for (; i + 4 <= end; i += 4) {
        int2 e0 = __ldg(&g_epack[i]);
        int2 e1 = __ldg(&g_epack[i + 1]);
        int2 e2 = __ldg(&g_epack[i + 2]);
        int2 e3 = __ldg(&g_epack[i + 3]);
        float v0 = __int_as_float(e0.y), v1 = __int_as_float(e1.y);
        float v2 = __int_as_float(e2.y), v3 = __int_as_float(e3.y);
        const float* h0 = cur + (size_t)e0.x * OUT_F;
        const float* h1 = cur + (size_t)e1.x * OUT_F;
        const float* h2 = cur + (size_t)e2.x * OUT_F;
        const float* h3 = cur + (size_t)e3.x * OUT_F;
        float x0 = __ldg(h0 + lane), x1 = __ldg(h0 + lane + 32), x2 = __ldg(h0 + lane + 64);
        float y0 = __ldg(h1 + lane), y1 = __ldg(h1 + lane + 32), y2 = __ldg(h1 + lane + 64);
        float z0 = __ldg(h2 + lane), z1 = __ldg(h2 + lane + 32), z2 = __ldg(h2 + lane + 64);
        float w0 = __ldg(h3 + lane), w1 = __ldg(h3 + lane + 32), w2 = __ldg(h3 + lane + 64);
        if (RELU_IN) {
            x0 = fmaxf(x0, 0.f); x1 = fmaxf(x1, 0.f); x2 = fmaxf(x2, 0.f);
            y0 = fmaxf(y0, 0.f); y1 = fmaxf(y1, 0.f); y2 = fmaxf(y2, 0.f);
            z0 = fmaxf(z0, 0.f); z1 = fmaxf(z1, 0.f); z2 = fmaxf(z2, 0.f);
            w0 = fmaxf(w0, 0.f); w1 = fmaxf(w1, 0.f); w2 = fmaxf(w2, 0.f);
        }
        a0 = fmaf(v0, x0, a0); a1 = fmaf(v0, x1, a1); a2 = fmaf(v0, x2, a2);
        a0 = fmaf(v1, y0, a0); a1 = fmaf(v1, y1, a1); a2 = fmaf(v1, y2, a2);
        a0 = fmaf(v2, z0, a0); a1 = fmaf(v2, z1, a1); a2 = fmaf(v2, z2, a2);
        a0 = fmaf(v3, w0, a0); a1 = fmaf(v3, w1, a1); a2 = fmaf(v3, w2, a2);
    }
    for (; i < end; ++i) {
        int2 e0 = __ldg(&g_epack[i]);
        float v0 = __int_as_float(e0.y);
        const float* h0 = cur + (size_t)e0.x * OUT_F;
        float x0 = __ldg(h0 + lane), x1 = __ldg(h0 + lane + 32), x2 = __ldg(h0 + lane + 64);
        if (RELU_IN) {
            x0 = fmaxf(x0, 0.f); x1 = fmaxf(x1, 0.f); x2 = fmaxf(x2, 0.f);
        }
        a0 = fmaf(v0, x0, a0); a1 = fmaf(v0, x1, a1); a2 = fmaf(v0, x2, a2);
    }

    const float* sp = sup + (size_t)warp * OUT_F;
    float r0 = fmaf(ALPHA, __ldg(sp + lane),      a0);
    float r1 = fmaf(ALPHA, __ldg(sp + lane + 32), a1);
    float r2 = fmaf(ALPHA, __ldg(sp + lane + 64), a2);
    if (RELU_OUT) {
        r0 = fmaxf(r0, 0.f); r1 = fmaxf(r1, 0.f); r2 = fmaxf(r2, 0.f);
    }
    float* o = out + (size_t)warp * OUT_F;
    o[lane] = r0; o[lane + 32] = r1; o[lane + 64] = r2;
}

// ---------------------------------------------------------------------------
extern "C" void kernel_launch(void* const* d_in, const int* in_sizes, int n_in,
                              void* d_out, int out_size)
{
    const float* x    = (const float*)d_in[0];
    const float* w    = (const float*)d_in[1];
    const int*   src  = (const int*)d_in[2];
    const int*   dst  = (const int*)d_in[3];
    const float* val  = (const float*)d_in[4];
    float*       out  = (float*)d_out;

    float *sup, *bufA, *bufB;
    cudaGetSymbolAddress((void**)&sup,  g_support);
    cudaGetSymbolAddress((void**)&bufA, g_bufA);
    cudaGetSymbolAddress((void**)&bufB, g_bufB);

    // Side stream + events for capture fork-join (host-side resources only).
    static cudaStream_t s_csr = nullptr;
    static cudaEvent_t  ev_fork = nullptr, ev_join = nullptr;
    if (!s_csr) {
        cudaStreamCreateWithFlags(&s_csr, cudaStreamNonBlocking);
        cudaEventCreateWithFlags(&ev_fork, cudaEventDisableTiming);
        cudaEventCreateWithFlags(&ev_join, cudaEventDisableTiming);
    }

    cudaFuncSetAttribute(gemm_mma_kernel,
                         cudaFuncAttributeMaxDynamicSharedMemorySize, GEMM_SMEM);

    // ---- fork: CSR build on side stream, GEMM on main stream ----
    cudaEventRecord(ev_fork, 0);
    cudaStreamWaitEvent(s_csr, ev_fork, 0);

    // branch A (main stream): W preconvert + GEMM
    wconv_kernel<<<(IN_F * OUT_F + 255) / 256, 256>>>(w);
    gemm_mma_kernel<<<(N_NODES + 127) / 128, 256, GEMM_SMEM>>>(x, sup);

    // branch B (side stream): CSR build (dst-sorted adjacency)
    zero_deg_kernel<<<(N_NODES + 255) / 256, 256, 0, s_csr>>>();
    hist_kernel<<<(N_EDGES + 255) / 256, 256, 0, s_csr>>>(dst);
    scan1_kernel<<<NBLK, SCAN_BLK, 0, s_csr>>>();
    scan2_kernel<<<1, 128, 0, s_csr>>>();
    scan3_kernel<<<(N_NODES + 255) / 256, 256, 0, s_csr>>>();
    fill_kernel<<<(N_EDGES + 255) / 256, 256, 0, s_csr>>>(src, dst, val);

    // ---- join ----
    cudaEventRecord(ev_join, s_csr);
    cudaStreamWaitEvent(0, ev_join, 0);

    // 10 propagation iterations, warp-per-node gather SpMM (fp32 state)
    const int spmmBlocks = (N_NODES * 32 + 255) / 256;
    const float* cur = sup;
    for (int it = 0; it < ITERS; ++it) {
        float* nxt = (it == ITERS - 1) ? out : ((it & 1) ? bufB : bufA);
        if (it == 0)
            spmm_kernel<0, 0><<<spmmBlocks, 256>>>(cur, sup, nxt);
        else if (it == ITERS - 1)
            spmm_kernel<1, 1><<<spmmBlocks, 256>>>(cur, sup, nxt);
        else
            spmm_kernel<1, 0><<<spmmBlocks, 256>>>(cur, sup, nxt);
        cur = nxt;
    }
}

// round 16
// speedup vs baseline: 1.7120x; 1.0027x over previous
#include <cuda_runtime.h>
#include <cuda_bf16.h>
#include <cstdint>

#define N_NODES  50000
#define N_EDGES  800000
#define IN_F     512
#define OUT_F    96
#define ALPHA    0.1f
#define ITERS    10
#define SCAN_BLK 512
#define NBLK     ((N_NODES + SCAN_BLK - 1) / SCAN_BLK)   // 98

// ---- device-global scratch (allocation-free per harness rules) -------------
__device__ float g_support[(size_t)N_NODES * OUT_F];
__device__ float g_bufA[(size_t)N_NODES * OUT_F];
__device__ float g_bufB[(size_t)N_NODES * OUT_F];
__device__ int   g_rowptr[N_NODES + 1];
__device__ int   g_cursor[N_NODES];
__device__ int   g_deg[N_NODES];
__device__ int   g_blocksum[NBLK];
__device__ int   g_blockoff[NBLK];
__device__ __align__(16) int2 g_epack[N_EDGES];   // {src, bits(0.9*val)}
// W split into bf16 hi/lo, transposed to [OUT_F][IN_F]
__device__ __align__(16) __nv_bfloat16 g_WhiT[(size_t)OUT_F * IN_F];
__device__ __align__(16) __nv_bfloat16 g_WloT[(size_t)OUT_F * IN_F];

// ---------------------------------------------------------------------------
// helpers for tensor-core GEMM
// ---------------------------------------------------------------------------
__device__ __forceinline__ uint32_t smem_u32(const void* p) {
    uint32_t a;
    asm("{ .reg .u64 t; cvta.to.shared.u64 t, %1; cvt.u32.u64 %0, t; }"
        : "=r"(a) : "l"(p));
    return a;
}

__device__ __forceinline__ void ldsm_x4(uint32_t* r, uint32_t addr) {
    asm volatile("ldmatrix.sync.aligned.m8n8.x4.shared.b16 {%0,%1,%2,%3}, [%4];"
                 : "=r"(r[0]), "=r"(r[1]), "=r"(r[2]), "=r"(r[3]) : "r"(addr));
}

__device__ __forceinline__ void mma_bf16(float* d, const uint32_t* a,
                                         uint32_t b0, uint32_t b1) {
    asm volatile("mma.sync.aligned.m16n8k16.row.col.f32.bf16.bf16.f32 "
                 "{%0,%1,%2,%3}, {%4,%5,%6,%7}, {%8,%9}, {%0,%1,%2,%3};"
                 : "+f"(d[0]), "+f"(d[1]), "+f"(d[2]), "+f"(d[3])
                 : "r"(a[0]), "r"(a[1]), "r"(a[2]), "r"(a[3]),
                   "r"(b0), "r"(b1));
}

// ---------------------------------------------------------------------------
// W preconvert: split fp32 W[512,96] into bf16 hi/lo, transposed [96][512]
// ---------------------------------------------------------------------------
__global__ void wconv_kernel(const float* __restrict__ W) {
    int i = blockIdx.x * blockDim.x + threadIdx.x;
    if (i < IN_F * OUT_F) {
        int k = i / OUT_F, n = i % OUT_F;
        float w = W[i];
        __nv_bfloat16 hi = __float2bfloat16_rn(w);
        float lo = w - __bfloat162float(hi);
        g_WhiT[(size_t)n * IN_F + k] = hi;
        g_WloT[(size_t)n * IN_F + k] = __float2bfloat16_rn(lo);
    }
}

// ---------------------------------------------------------------------------
// GEMM via mma.sync bf16 split: support = X @ W
// ---------------------------------------------------------------------------
#define SMS 144   // bytes per smem row
#define A_HI_OFF 0
#define A_LO_OFF 18432         // 128*144
#define B_HI_OFF 36864
#define B_LO_OFF 50688
#define GEMM_SMEM 64512

__global__ __launch_bounds__(256, 2) void gemm_mma_kernel(
    const float* __restrict__ X, float* __restrict__ out)
{
    extern __shared__ char sm[];
    char* As_hi = sm + A_HI_OFF;
    char* As_lo = sm + A_LO_OFF;
    char* Bs_hi = sm + B_HI_OFF;
    char* Bs_lo = sm + B_LO_OFF;

    const int tid  = threadIdx.x;
    const int lane = tid & 31;
    const int wid  = tid >> 5;
    const int wm   = wid >> 1;
    const int wn   = wid & 1;
    const int ctaM = blockIdx.x * 128;

    float acc[2][6][4];
#pragma unroll
    for (int mt = 0; mt < 2; ++mt)
#pragma unroll
        for (int nt = 0; nt < 6; ++nt)
#pragma unroll
            for (int r = 0; r < 4; ++r) acc[mt][nt][r] = 0.0f;

    const uint32_t a_hi = smem_u32(As_hi);
    const uint32_t a_lo = smem_u32(As_lo);
    const uint32_t b_hi = smem_u32(Bs_hi);
    const uint32_t b_lo = smem_u32(Bs_lo);

    const int a_row = ((lane >> 3) & 1) * 8 + (lane & 7);
    const int a_kh  = lane >> 4;
    const int b_row = ((lane >> 4) & 1) * 8 + (lane & 7);
    const int b_kh  = (lane >> 3) & 1;

    for (int k0 = 0; k0 < IN_F; k0 += 64) {
#pragma unroll
        for (int j = 0; j < 8; ++j) {
            int i   = tid + j * 256;
            int row = i >> 4;
            int kg  = i & 15;
            int grow = ctaM + row;
            if (grow >= N_NODES) grow = N_NODES - 1;
            float4 v = *reinterpret_cast<const float4*>(
                X + (size_t)grow * IN_F + k0 + kg * 4);
            __nv_bfloat16 h0 = __float2bfloat16_rn(v.x);
            __nv_bfloat16 h1 = __float2bfloat16_rn(v.y);
            __nv_bfloat16 h2 = __float2bfloat16_rn(v.z);
            __nv_bfloat16 h3 = __float2bfloat16_rn(v.w);
            char* ph = As_hi + row * SMS + kg * 8;
            *reinterpret_cast<__nv_bfloat162*>(ph)     = __halves2bfloat162(h0, h1);
            *reinterpret_cast<__nv_bfloat162*>(ph + 4) = __halves2bfloat162(h2, h3);
            __nv_bfloat16 l0 = __float2bfloat16_rn(v.x - __bfloat162float(h0));
            __nv_bfloat16 l1 = __float2bfloat16_rn(v.y - __bfloat162float(h1));
            __nv_bfloat16 l2 = __float2bfloat16_rn(v.z - __bfloat162float(h2));
            __nv_bfloat16 l3 = __float2bfloat16_rn(v.w - __bfloat162float(h3));
            char* pl = As_lo + row * SMS + kg * 8;
            *reinterpret_cast<__nv_bfloat162*>(pl)     = __halves2bfloat162(l0, l1);
            *reinterpret_cast<__nv_bfloat162*>(pl + 4) = __halves2bfloat162(l2, l3);
        }
#pragma unroll
        for (int j = 0; j < 3; ++j) {
            int i   = tid + j * 256;
            int row = i >> 3;
            int kg  = i & 7;
            size_t goff = ((size_t)row * IN_F + k0) * 2 + kg * 16;
            *reinterpret_cast<uint4*>(Bs_hi + row * SMS + kg * 16) =
                *reinterpret_cast<const uint4*>(
                    reinterpret_cast<const char*>(g_WhiT) + goff);
            *reinterpret_cast<uint4*>(Bs_lo + row * SMS + kg * 16) =
                *reinterpret_cast<const uint4*>(
                    reinterpret_cast<const char*>(g_WloT) + goff);
        }
        __syncthreads();

#pragma unroll
        for (int ks = 0; ks < 4; ++ks) {
            uint32_t Ah[2][4], Al[2][4];
#pragma unroll
            for (int mt = 0; mt < 2; ++mt) {
                uint32_t off = (uint32_t)((wm * 32 + mt * 16 + a_row) * SMS
                                          + ks * 32 + a_kh * 16);
                ldsm_x4(Ah[mt], a_hi + off);
                ldsm_x4(Al[mt], a_lo + off);
            }
            uint32_t Bh[3][4], Bl[3][4];
#pragma unroll
            for (int np = 0; np < 3; ++np) {
                uint32_t off = (uint32_t)((wn * 48 + np * 16 + b_row) * SMS
                                          + ks * 32 + b_kh * 16);
                ldsm_x4(Bh[np], b_hi + off);
                ldsm_x4(Bl[np], b_lo + off);
            }
#pragma unroll
            for (int mt = 0; mt < 2; ++mt)
#pragma unroll
                for (int nt = 0; nt < 6; ++nt) {
                    uint32_t bh0 = Bh[nt >> 1][(nt & 1) * 2];
                    uint32_t bh1 = Bh[nt >> 1][(nt & 1) * 2 + 1];
                    uint32_t bl0 = Bl[nt >> 1][(nt & 1) * 2];
                    uint32_t bl1 = Bl[nt >> 1][(nt & 1) * 2 + 1];
                    mma_bf16(acc[mt][nt], Ah[mt], bh0, bh1);
                    mma_bf16(acc[mt][nt], Ah[mt], bl0, bl1);
                    mma_bf16(acc[mt][nt], Al[mt], bh0, bh1);
                }
        }
        __syncthreads();
    }

#pragma unroll
    for (int mt = 0; mt < 2; ++mt) {
        int row0 = ctaM + wm * 32 + mt * 16 + (lane >> 2);
#pragma unroll
        for (int nt = 0; nt < 6; ++nt) {
            int col = wn * 48 + nt * 8 + (lane & 3) * 2;
            if (row0 < N_NODES) {
                float2 v = make_float2(acc[mt][nt][0], acc[mt][nt][1]);
                *reinterpret_cast<float2*>(out + (size_t)row0 * OUT_F + col) = v;
            }
            int row1 = row0 + 8;
            if (row1 < N_NODES) {
                float2 v = make_float2(acc[mt][nt][2], acc[mt][nt][3]);
                *reinterpret_cast<float2*>(out + (size_t)row1 * OUT_F + col) = v;
            }
        }
    }
}

// ---------------------------------------------------------------------------
// CSR build: histogram -> scan -> fill (packed src+val records)
// ---------------------------------------------------------------------------
__global__ void zero_deg_kernel() {
    int i = blockIdx.x * blockDim.x + threadIdx.x;
    if (i < N_NODES) g_deg[i] = 0;
}

__global__ void hist_kernel(const int* __restrict__ dst) {
    int i = blockIdx.x * blockDim.x + threadIdx.x;
    if (i < N_EDGES) atomicAdd(&g_deg[dst[i]], 1);
}

__global__ __launch_bounds__(SCAN_BLK) void scan1_kernel() {
    __shared__ int sh[SCAN_BLK];
    int t = threadIdx.x;
    int gi = blockIdx.x * SCAN_BLK + t;
    int v = (gi < N_NODES) ? g_deg[gi] : 0;
    sh[t] = v;
    __syncthreads();
#pragma unroll
    for (int off = 1; off < SCAN_BLK; off <<= 1) {
        int x = (t >= off) ? sh[t - off] : 0;
        __syncthreads();
        sh[t] += x;
        __syncthreads();
    }
    if (gi < N_NODES) g_rowptr[gi] = sh[t] - v;
    if (t == SCAN_BLK - 1) g_blocksum[blockIdx.x] = sh[t];
}

__global__ __launch_bounds__(128) void scan2_kernel() {
    __shared__ int sh[128];
    int t = threadIdx.x;
    int v = (t < NBLK) ? g_blocksum[t] : 0;
    sh[t] = v;
    __syncthreads();
#pragma unroll
    for (int off = 1; off < 128; off <<= 1) {
        int x = (t >= off) ? sh[t - off] : 0;
        __syncthreads();
        sh[t] += x;
        __syncthreads();
    }
    if (t < NBLK) g_blockoff[t] = sh[t] - v;
}

__global__ void scan3_kernel() {
    int i = blockIdx.x * blockDim.x + threadIdx.x;
    if (i < N_NODES) {
        int r = g_rowptr[i] + g_blockoff[i / SCAN_BLK];
        g_rowptr[i] = r;
        g_cursor[i] = r;
    }
    if (i == 0) g_rowptr[N_NODES] = N_EDGES;
}

__global__ void fill_kernel(const int* __restrict__ src,
                            const int* __restrict__ dst,
                            const float* __restrict__ val) {
    int i = blockIdx.x * blockDim.x + threadIdx.x;
    if (i < N_EDGES) {
        int pos = atomicAdd(&g_cursor[dst[i]], 1);
        g_epack[pos] = make_int2(src[i],
                                 __float_as_int(val[i] * (1.0f - ALPHA)));
    }
}

// ---------------------------------------------------------------------------
// SpMM (gather, warp-per-destination-node), fused residual + lazy ReLU.
// Proven best configuration (packed int2 edge records, unroll 4).
// ---------------------------------------------------------------------------
template <int RELU_IN, int RELU_OUT>
__global__ __launch_bounds__(256) void spmm_kernel(
    const float* __restrict__ cur, const float* __restrict__ sup,
    float* __restrict__ out)
{
    int warp = (blockIdx.x * 256 + threadIdx.x) >> 5;
    int lane = threadIdx.x & 31;
    if (warp >= N_NODES) return;

    int beg = g_rowptr[warp];
    int end = g_rowptr[warp + 1];

    float a0 = 0.f, a1 = 0.f, a2 = 0.f;

    int i = beg;
    for (; i + 4 <= end; i += 4) {
        int2 e0 = __ldg(&g_epack[i]);
        int2 e1 = __ldg(&g_epack[i + 1]);
        int2 e2 = __ldg(&g_epack[i + 2]);
        int2 e3 = __ldg(&g_epack[i + 3]);
        float v0 = __int_as_float(e0.y), v1 = __int_as_float(e1.y);
        float v2 = __int_as_float(e2.y), v3 = __int_as_float(e3.y);
        const float* h0 = cur + (size_t)e0.x * OUT_F;
        const float* h1 = cur + (size_t)e1.x * OUT_F;
        const float* h2 = cur + (size_t)e2.x * OUT_F;
        const float* h3 = cur + (size_t)e3.x * OUT_F;
        float x0 = __ldg(h0 + lane), x1 = __ldg(h0 + lane + 32), x2 = __ldg(h0 + lane + 64);
        float y0 = __ldg(h1 + lane), y1 = __ldg(h1 + lane + 32), y2 = __ldg(h1 + lane + 64);
        float z0 = __ldg(h2 + lane), z1 = __ldg(h2 + lane + 32), z2 = __ldg(h2 + lane + 64);
        float w0 = __ldg(h3 + lane), w1 = __ldg(h3 + lane + 32), w2 = __ldg(h3 + lane + 64);
        if (RELU_IN) {
            x0 = fmaxf(x0, 0.f); x1 = fmaxf(x1, 0.f); x2 = fmaxf(x2, 0.f);
            y0 = fmaxf(y0, 0.f); y1 = fmaxf(y1, 0.f); y2 = fmaxf(y2, 0.f);
            z0 = fmaxf(z0, 0.f); z1 = fmaxf(z1, 0.f); z2 = fmaxf(z2, 0.f);
            w0 = fmaxf(w0, 0.f); w1 = fmaxf(w1, 0.f); w2 = fmaxf(w2, 0.f);
        }
        a0 = fmaf(v0, x0, a0); a1 = fmaf(v0, x1, a1); a2 = fmaf(v0, x2, a2);
        a0 = fmaf(v1, y0, a0); a1 = fmaf(v1, y1, a1); a2 = fmaf(v1, y2, a2);
        a0 = fmaf(v2, z0, a0); a1 = fmaf(v2, z1, a1); a2 = fmaf(v2, z2, a2);
        a0 = fmaf(v3, w0, a0); a1 = fmaf(v3, w1, a1); a2 = fmaf(v3, w2, a2);
    }
    for (; i < end; ++i) {
        int2 e0 = __ldg(&g_epack[i]);
        float v0 = __int_as_float(e0.y);
        const float* h0 = cur + (size_t)e0.x * OUT_F;
        float x0 = __ldg(h0 + lane), x1 = __ldg(h0 + lane + 32), x2 = __ldg(h0 + lane + 64);
        if (RELU_IN) {
            x0 = fmaxf(x0, 0.f); x1 = fmaxf(x1, 0.f); x2 = fmaxf(x2, 0.f);
        }
        a0 = fmaf(v0, x0, a0); a1 = fmaf(v0, x1, a1); a2 = fmaf(v0, x2, a2);
    }

    const float* sp = sup + (size_t)warp * OUT_F;
    float r0 = fmaf(ALPHA, __ldg(sp + lane),      a0);
    float r1 = fmaf(ALPHA, __ldg(sp + lane + 32), a1);
    float r2 = fmaf(ALPHA, __ldg(sp + lane + 64), a2);
    if (RELU_OUT) {
        r0 = fmaxf(r0, 0.f); r1 = fmaxf(r1, 0.f); r2 = fmaxf(r2, 0.f);
    }
    float* o = out + (size_t)warp * OUT_F;
    o[lane] = r0; o[lane + 32] = r1; o[lane + 64] = r2;
}

// ---------------------------------------------------------------------------
extern "C" void kernel_launch(void* const* d_in, const int* in_sizes, int n_in,
                              void* d_out, int out_size)
{
    const float* x    = (const float*)d_in[0];
    const float* w    = (const float*)d_in[1];
    const int*   src  = (const int*)d_in[2];
    const int*   dst  = (const int*)d_in[3];
    const float* val  = (const float*)d_in[4];
    float*       out  = (float*)d_out;

    float *sup, *bufA, *bufB;
    cudaGetSymbolAddress((void**)&sup,  g_support);
    cudaGetSymbolAddress((void**)&bufA, g_bufA);
    cudaGetSymbolAddress((void**)&bufB, g_bufB);

    // Side stream + events for capture fork-join (host-side resources only).
    static cudaStream_t s_csr = nullptr;
    static cudaEvent_t  ev_fork = nullptr, ev_join = nullptr;
    if (!s_csr) {
        cudaStreamCreateWithFlags(&s_csr, cudaStreamNonBlocking);
        cudaEventCreateWithFlags(&ev_fork, cudaEventDisableTiming);
        cudaEventCreateWithFlags(&ev_join, cudaEventDisableTiming);
    }

    cudaFuncSetAttribute(gemm_mma_kernel,
                         cudaFuncAttributeMaxDynamicSharedMemorySize, GEMM_SMEM);

    // ---- fork: CSR build on side stream, GEMM on main stream ----
    cudaEventRecord(ev_fork, 0);
    cudaStreamWaitEvent(s_csr, ev_fork, 0);

    // branch A (main stream): W preconvert + GEMM
    wconv_kernel<<<(IN_F * OUT_F + 255) / 256, 256>>>(w);
    gemm_mma_kernel<<<(N_NODES + 127) / 128, 256, GEMM_SMEM>>>(x, sup);

    // branch B (side stream): CSR build (dst-sorted adjacency)
    zero_deg_kernel<<<(N_NODES + 255) / 256, 256, 0, s_csr>>>();
    hist_kernel<<<(N_EDGES + 255) / 256, 256, 0, s_csr>>>(dst);
    scan1_kernel<<<NBLK, SCAN_BLK, 0, s_csr>>>();
    scan2_kernel<<<1, 128, 0, s_csr>>>();
    scan3_kernel<<<(N_NODES + 255) / 256, 256, 0, s_csr>>>();
    fill_kernel<<<(N_EDGES + 255) / 256, 256, 0, s_csr>>>(src, dst, val);

    // ---- join ----
    cudaEventRecord(ev_join, s_csr);
    cudaStreamWaitEvent(0, ev_join, 0);

    // 10 propagation iterations, warp-per-node gather SpMM (fp32 state)
    const int spmmBlocks = (N_NODES * 32 + 255) / 256;
    const float* cur = sup;
    for (int it = 0; it < ITERS; ++it) {
        float* nxt = (it == ITERS - 1) ? out : ((it & 1) ? bufB : bufA);
        if (it == 0)
            spmm_kernel<0, 0><<<spmmBlocks, 256>>>(cur, sup, nxt);
        else if (it == ITERS - 1)
            spmm_kernel<1, 1><<<spmmBlocks, 256>>>(cur, sup, nxt);
        else
            spmm_kernel<1, 0><<<spmmBlocks, 256>>>(cur, sup, nxt);
        cur = nxt;
    }
}